// round 2
// baseline (speedup 1.0000x reference)
#include <cuda_runtime.h>
#include <cfloat>
#include <climits>
#include <math.h>

// Problem constants (fixed shapes per reference)
#define NPTS     4096
#define G_TOTAL  65536
#define NCELL1D  64
#define NCELLS   (NCELL1D * NCELL1D)
#define INV_CELL (1.0f / 16.0f)

#define NEG_INF_F (__int_as_float(0xff800000))

// Scratch (static device globals — no allocation)
__device__ float4 g_pts[NPTS];       // px, py, p2, score (cell-sorted)
__device__ int    g_pid[NPTS];       // original point index (cell-sorted)
__device__ int    g_off[NCELLS + 1]; // exclusive prefix offsets per cell

// ---------------------------------------------------------------------------
// Kernel 1: bin the 4096 points into a 64x64 spatial hash.
// Single block of 1024 threads: histogram + scan + scatter, all via smem.
// ---------------------------------------------------------------------------
__global__ __launch_bounds__(1024) void build_bins_kernel(
    const float4* __restrict__ pos,      // (NPTS, 4)
    const float*  __restrict__ scores)   // (NPTS,)
{
    __shared__ int s_cnt[NCELLS];   // histogram, later reused as scatter cursor
    __shared__ int s_sum[1024];     // per-thread sums for block scan

    const int tid = threadIdx.x;

    #pragma unroll
    for (int i = 0; i < 4; i++) s_cnt[tid + i * 1024] = 0;
    __syncthreads();

    float px[4], py[4], p2[4], sc[4];
    int   cell[4];

    #pragma unroll
    for (int i = 0; i < 4; i++) {
        const int t = tid + i * 1024;
        const float4 p = pos[t];
        px[i] = p.x; py[i] = p.y;
        // p2 with the reference's rounding: round(px*px) + round(py*py)
        p2[i] = __fadd_rn(__fmul_rn(p.x, p.x), __fmul_rn(p.y, p.y));
        sc[i] = scores[t];
        int cx = (int)floorf(p.x * INV_CELL);
        int cy = (int)floorf(p.y * INV_CELL);
        cx = min(NCELL1D - 1, max(0, cx));
        cy = min(NCELL1D - 1, max(0, cy));
        cell[i] = cy * NCELL1D + cx;
        atomicAdd(&s_cnt[cell[i]], 1);
    }
    __syncthreads();

    // Each thread owns 4 consecutive cells: local counts + block-wide scan.
    const int c0 = s_cnt[4 * tid + 0];
    const int c1 = s_cnt[4 * tid + 1];
    const int c2 = s_cnt[4 * tid + 2];
    const int c3 = s_cnt[4 * tid + 3];
    const int tsum = c0 + c1 + c2 + c3;
    s_sum[tid] = tsum;
    __syncthreads();

    // Hillis-Steele inclusive scan over 1024 entries.
    for (int off = 1; off < 1024; off <<= 1) {
        const int v   = s_sum[tid];
        const int add = (tid >= off) ? s_sum[tid - off] : 0;
        __syncthreads();
        s_sum[tid] = v + add;
        __syncthreads();
    }
    const int excl = s_sum[tid] - tsum;

    const int o0 = excl;
    const int o1 = o0 + c0;
    const int o2 = o1 + c1;
    const int o3 = o2 + c2;
    g_off[4 * tid + 0] = o0;
    g_off[4 * tid + 1] = o1;
    g_off[4 * tid + 2] = o2;
    g_off[4 * tid + 3] = o3;
    // Reuse s_cnt as the scatter cursor (start offsets).
    s_cnt[4 * tid + 0] = o0;
    s_cnt[4 * tid + 1] = o1;
    s_cnt[4 * tid + 2] = o2;
    s_cnt[4 * tid + 3] = o3;
    if (tid == 0) g_off[NCELLS] = NPTS;
    __syncthreads();

    #pragma unroll
    for (int i = 0; i < 4; i++) {
        const int dst = atomicAdd(&s_cnt[cell[i]], 1);
        g_pts[dst] = make_float4(px[i], py[i], p2[i], sc[i]);
        g_pid[dst] = tid + i * 1024;
    }
}

// ---------------------------------------------------------------------------
// Kernel 2: one thread per grid point — windowed top-4 + filter + select.
// ---------------------------------------------------------------------------
__global__ __launch_bounds__(256) void pump_main_kernel(
    const float2* __restrict__ grid,     // (G, 2)
    const float4* __restrict__ pos,      // (NPTS, 4)
    const float*  __restrict__ accu,     // (G, 6)
    const float*  __restrict__ scale_p,  // scalar
    const float*  __restrict__ code_p,   // scalar
    float*        __restrict__ out)      // (G, 6)
{
    const int g = blockIdx.x * blockDim.x + threadIdx.x;
    if (g >= G_TOTAL) return;

    const float2 gp = grid[g];
    const float gx = gp.x, gy = gp.y;
    const float g2 = __fadd_rn(__fmul_rn(gx, gx), __fmul_rn(gy, gy));

    const float scale = *scale_p;
    const float dist_max = __fsub_rn(__fmul_rn(8.0f, scale), 1e-7f);
    const float r = dist_max;

    int cx0 = (int)floorf((gx - r) * INV_CELL);
    int cx1 = (int)floorf((gx + r) * INV_CELL);
    int cy0 = (int)floorf((gy - r) * INV_CELL);
    int cy1 = (int)floorf((gy + r) * INV_CELL);
    cx0 = min(NCELL1D - 1, max(0, cx0));
    cx1 = min(NCELL1D - 1, max(0, cx1));
    cy0 = min(NCELL1D - 1, max(0, cy0));
    cy1 = min(NCELL1D - 1, max(0, cy1));

    // Top-4 by lexicographic (d2, index) — matches top_k tie-breaking.
    float d2a = FLT_MAX, d2b = FLT_MAX, d2c = FLT_MAX, d2d = FLT_MAX;
    int   ida = INT_MAX, idb = INT_MAX, idc = INT_MAX, idd = INT_MAX;
    float sca = 0.0f,    scb = 0.0f,    scc = 0.0f,    scd = 0.0f;

    for (int cy = cy0; cy <= cy1; cy++) {
        const int rowc = cy * NCELL1D;
        for (int cx = cx0; cx <= cx1; cx++) {
            const int c = rowc + cx;
            const int s = g_off[c];
            const int e = g_off[c + 1];
            for (int k = s; k < e; k++) {
                const float4 p = g_pts[k];
                const int pid = g_pid[k];
                // Reference rounding: dot = fma(py,gy, round(px*gx));
                // d2 = (p2 + g2) - 2*dot
                const float dot = __fmaf_rn(p.y, gy, __fmul_rn(p.x, gx));
                const float d2 = __fsub_rn(__fadd_rn(p.z, g2),
                                           __fmul_rn(2.0f, dot));
                // lexicographic insert
                if (d2 < d2d || (d2 == d2d && pid < idd)) {
                    d2d = d2; idd = pid; scd = p.w;
                    if (d2d < d2c || (d2d == d2c && idd < idc)) {
                        float td = d2c; int ti = idc; float ts = scc;
                        d2c = d2d; idc = idd; scc = scd;
                        d2d = td; idd = ti; scd = ts;
                        if (d2c < d2b || (d2c == d2b && idc < idb)) {
                            td = d2b; ti = idb; ts = scb;
                            d2b = d2c; idb = idc; scb = scc;
                            d2c = td; idc = ti; scc = ts;
                            if (d2b < d2a || (d2b == d2a && idb < ida)) {
                                td = d2a; ti = ida; ts = sca;
                                d2a = d2b; ida = idb; sca = scb;
                                d2b = td; idb = ti; scb = ts;
                            }
                        }
                    }
                }
            }
        }
    }

    // Finalize: d = sqrt(max(d2,1e-12)); filter (d <= 2*d0) & (d < dist_max);
    // pick max score, first occurrence wins ties (strict >).
    const float d0 = sqrtf(fmaxf(d2a, 1e-12f));
    const float thr = __fmul_rn(2.0f, d0);  // exact (power of 2)

    float best = NEG_INF_F;
    int bestid = 0;
    {
        const float dk = d0;
        if (dk <= thr && dk < dist_max && sca > best) { best = sca; bestid = ida; }
    }
    {
        const float dk = sqrtf(fmaxf(d2b, 1e-12f));
        if (dk <= thr && dk < dist_max && scb > best) { best = scb; bestid = idb; }
    }
    {
        const float dk = sqrtf(fmaxf(d2c, 1e-12f));
        if (dk <= thr && dk < dist_max && scc > best) { best = scc; bestid = idc; }
    }
    {
        const float dk = sqrtf(fmaxf(d2d, 1e-12f));
        if (dk <= thr && dk < dist_max && scd > best) { best = scd; bestid = idd; }
    }

    // Rows are 24 bytes -> float2-aligned.
    const float2* acc2 = (const float2*)accu;
    float2* out2 = (float2*)out;
    const float2 a01 = acc2[g * 3 + 0];
    const float2 a23 = acc2[g * 3 + 1];
    const float2 a45 = acc2[g * 3 + 2];

    if (best > a45.x) {
        const float4 pr = pos[bestid];
        const float code = *code_p;
        out2[g * 3 + 0] = make_float2(pr.x, pr.y);
        out2[g * 3 + 1] = make_float2(pr.z, pr.w);
        out2[g * 3 + 2] = make_float2(best, code);
    } else {
        out2[g * 3 + 0] = a01;
        out2[g * 3 + 1] = a23;
        out2[g * 3 + 2] = a45;
    }
}

// ---------------------------------------------------------------------------
// Inputs (metadata order): pos (4096,4) f32, scores (4096,) f32,
// grid (65536,2) f32, accu (65536,6) f32, scale () f32, code () f32.
// Output: (65536, 6) f32.
// ---------------------------------------------------------------------------
extern "C" void kernel_launch(void* const* d_in, const int* in_sizes, int n_in,
                              void* d_out, int out_size)
{
    const float4* pos    = (const float4*)d_in[0];
    const float*  scores = (const float*) d_in[1];
    const float2* grid   = (const float2*)d_in[2];
    const float*  accu   = (const float*) d_in[3];
    const float*  scale  = (const float*) d_in[4];
    const float*  code   = (const float*) d_in[5];
    float* out = (float*)d_out;

    build_bins_kernel<<<1, 1024>>>(pos, scores);
    pump_main_kernel<<<G_TOTAL / 256, 256>>>(grid, pos, accu, scale, code, out);
}

// round 3
// speedup vs baseline: 1.1081x; 1.1081x over previous
#include <cuda_runtime.h>
#include <cfloat>
#include <climits>
#include <math.h>

#define NPTS     4096
#define G_TOTAL  65536
#define NCELL1D  64
#define NCELLS   (NCELL1D * NCELL1D)
#define INV_CELL (1.0f / 16.0f)
#define NEG_INF_F (__int_as_float(0xff800000))

// smem staging capacity for the main kernel (points per block window)
#define CAP      1024
#define MAXROWS  4

// Scratch (static device globals — no allocation)
__device__ float4 g_pts[NPTS];       // px, py, p2, score (cell-sorted)
__device__ int    g_pid[NPTS];       // original point index (cell-sorted)
__device__ int    g_off[NCELLS + 1]; // exclusive prefix offsets per cell

// ---------------------------------------------------------------------------
// Kernel 1: bin the 4096 points into a 64x64 spatial hash.
// Single block of 1024 threads: histogram + warp-shuffle scan + scatter.
// ---------------------------------------------------------------------------
__global__ __launch_bounds__(1024) void build_bins_kernel(
    const float4* __restrict__ pos,
    const float*  __restrict__ scores)
{
    __shared__ int s_cnt[NCELLS];   // histogram, later reused as scatter cursor
    __shared__ int s_warp[32];      // per-warp scan sums

    const int tid  = threadIdx.x;
    const int lane = tid & 31;
    const int warp = tid >> 5;

    #pragma unroll
    for (int i = 0; i < 4; i++) s_cnt[tid + i * 1024] = 0;
    __syncthreads();

    float px[4], py[4], p2[4], sc[4];
    int   cell[4];

    #pragma unroll
    for (int i = 0; i < 4; i++) {
        const int t = tid + i * 1024;
        const float4 p = pos[t];
        px[i] = p.x; py[i] = p.y;
        // reference rounding: round(px*px) + round(py*py)
        p2[i] = __fadd_rn(__fmul_rn(p.x, p.x), __fmul_rn(p.y, p.y));
        sc[i] = scores[t];
        int cx = (int)floorf(p.x * INV_CELL);
        int cy = (int)floorf(p.y * INV_CELL);
        cx = min(NCELL1D - 1, max(0, cx));
        cy = min(NCELL1D - 1, max(0, cy));
        cell[i] = cy * NCELL1D + cx;
        atomicAdd(&s_cnt[cell[i]], 1);
    }
    __syncthreads();

    // Each thread owns 4 consecutive cells.
    const int c0 = s_cnt[4 * tid + 0];
    const int c1 = s_cnt[4 * tid + 1];
    const int c2 = s_cnt[4 * tid + 2];
    const int c3 = s_cnt[4 * tid + 3];
    const int tsum = c0 + c1 + c2 + c3;

    // Warp inclusive scan of tsum.
    int v = tsum;
    #pragma unroll
    for (int o = 1; o < 32; o <<= 1) {
        const int n = __shfl_up_sync(0xffffffffu, v, o);
        if (lane >= o) v += n;
    }
    if (lane == 31) s_warp[warp] = v;
    __syncthreads();

    // Warp 0 scans the 32 warp sums (inclusive).
    if (warp == 0) {
        int w = s_warp[lane];
        #pragma unroll
        for (int o = 1; o < 32; o <<= 1) {
            const int n = __shfl_up_sync(0xffffffffu, w, o);
            if (lane >= o) w += n;
        }
        s_warp[lane] = w;
    }
    __syncthreads();

    const int excl = (warp > 0 ? s_warp[warp - 1] : 0) + v - tsum;

    const int o0 = excl;
    const int o1 = o0 + c0;
    const int o2 = o1 + c1;
    const int o3 = o2 + c2;
    g_off[4 * tid + 0] = o0;
    g_off[4 * tid + 1] = o1;
    g_off[4 * tid + 2] = o2;
    g_off[4 * tid + 3] = o3;
    if (tid == 0) g_off[NCELLS] = NPTS;
    __syncthreads();   // s_cnt reuse below must not race with reads above

    // Reuse s_cnt as scatter cursor.
    s_cnt[4 * tid + 0] = o0;
    s_cnt[4 * tid + 1] = o1;
    s_cnt[4 * tid + 2] = o2;
    s_cnt[4 * tid + 3] = o3;
    __syncthreads();

    #pragma unroll
    for (int i = 0; i < 4; i++) {
        const int dst = atomicAdd(&s_cnt[cell[i]], 1);
        g_pts[dst] = make_float4(px[i], py[i], p2[i], sc[i]);
        g_pid[dst] = tid + i * 1024;
    }
}

// ---------------------------------------------------------------------------
// Lexicographic (d2, pid) top-4 insertion — matches top_k tie-breaking.
// ---------------------------------------------------------------------------
__device__ __forceinline__ void insert4(
    float d2, int pid, float sc,
    float& d2a, float& d2b, float& d2c, float& d2d,
    int& ida, int& idb, int& idc, int& idd,
    float& sca, float& scb, float& scc, float& scd)
{
    if (d2 < d2d || (d2 == d2d && pid < idd)) {
        d2d = d2; idd = pid; scd = sc;
        if (d2d < d2c || (d2d == d2c && idd < idc)) {
            float td = d2c; int ti = idc; float ts = scc;
            d2c = d2d; idc = idd; scc = scd;
            d2d = td; idd = ti; scd = ts;
            if (d2c < d2b || (d2c == d2b && idc < idb)) {
                td = d2b; ti = idb; ts = scb;
                d2b = d2c; idb = idc; scb = scc;
                d2c = td; idc = ti; scc = ts;
                if (d2b < d2a || (d2b == d2a && idb < ida)) {
                    td = d2a; ti = ida; ts = sca;
                    d2a = d2b; ida = idb; sca = scb;
                    d2b = td; idb = ti; scb = ts;
                }
            }
        }
    }
}

// ---------------------------------------------------------------------------
// Kernel 2: one thread per grid point. Block = one grid row -> all threads
// share the same cy window; points for that window are CONTIGUOUS in g_pts
// (cells are row-major, points cell-sorted). Stage them in smem once.
// ---------------------------------------------------------------------------
__global__ __launch_bounds__(256) void pump_main_kernel(
    const float2* __restrict__ grid,
    const float4* __restrict__ pos,
    const float*  __restrict__ accu,
    const float*  __restrict__ scale_p,
    const float*  __restrict__ code_p,
    float*        __restrict__ out)
{
    __shared__ float s_px[CAP], s_py[CAP], s_p2[CAP], s_sc[CAP];
    __shared__ int   s_id[CAP];
    __shared__ int   s_off[MAXROWS * NCELL1D + 1];
    __shared__ int   s_cyA, s_cyB;

    const int tid = threadIdx.x;
    const int g = blockIdx.x * 256 + tid;

    const float2 gp = grid[g];
    const float gx = gp.x, gy = gp.y;
    const float g2 = __fadd_rn(__fmul_rn(gx, gx), __fmul_rn(gy, gy));

    const float scale = *scale_p;
    const float dist_max = __fsub_rn(__fmul_rn(8.0f, scale), 1e-7f);
    const float r = dist_max;

    int cx0 = (int)floorf((gx - r) * INV_CELL);
    int cx1 = (int)floorf((gx + r) * INV_CELL);
    int cy0 = (int)floorf((gy - r) * INV_CELL);
    int cy1 = (int)floorf((gy + r) * INV_CELL);
    cx0 = min(NCELL1D - 1, max(0, cx0));
    cx1 = min(NCELL1D - 1, max(0, cx1));
    cy0 = min(NCELL1D - 1, max(0, cy0));
    cy1 = min(NCELL1D - 1, max(0, cy1));

    // Block-wide cy window (identical across threads for the real grid, but
    // reduced for generality).
    if (tid == 0) { s_cyA = cy0; s_cyB = cy1; }
    __syncthreads();
    atomicMin(&s_cyA, cy0);
    atomicMax(&s_cyB, cy1);
    __syncthreads();
    const int cyA = s_cyA;
    const int cyB = s_cyB;

    const int nRows = cyB - cyA + 1;
    const int offBase = cyA * NCELL1D;
    const int nOff = nRows * NCELL1D;          // +1 handled below
    const int pA = g_off[offBase];
    const int pB = g_off[offBase + nOff];
    const int count = pB - pA;

    const bool use_smem = (nRows <= MAXROWS) && (count <= CAP);

    // Top-4 state
    float d2a = FLT_MAX, d2b = FLT_MAX, d2c = FLT_MAX, d2d = FLT_MAX;
    int   ida = INT_MAX, idb = INT_MAX, idc = INT_MAX, idd = INT_MAX;
    float sca = 0.0f,    scb = 0.0f,    scc = 0.0f,    scd = 0.0f;

    if (use_smem) {
        for (int i = tid; i <= nOff; i += 256)
            s_off[i] = g_off[offBase + i] - pA;
        for (int i = tid; i < count; i += 256) {
            const float4 p = g_pts[pA + i];
            s_px[i] = p.x; s_py[i] = p.y; s_p2[i] = p.z; s_sc[i] = p.w;
            s_id[i] = g_pid[pA + i];
        }
        __syncthreads();

        #pragma unroll 2
        for (int cy = cy0; cy <= cy1; cy++) {
            const int rb = (cy - cyA) * NCELL1D;
            const int s = s_off[rb + cx0];
            const int e = s_off[rb + cx1 + 1];   // cells contiguous within a row
            for (int k = s; k < e; k++) {
                const float dot = __fmaf_rn(s_py[k], gy, __fmul_rn(s_px[k], gx));
                const float d2 = __fsub_rn(__fadd_rn(s_p2[k], g2),
                                           __fmul_rn(2.0f, dot));
                insert4(d2, s_id[k], s_sc[k],
                        d2a, d2b, d2c, d2d, ida, idb, idc, idd,
                        sca, scb, scc, scd);
            }
        }
    } else {
        // Fallback: read directly from global (correct for any input).
        for (int cy = cy0; cy <= cy1; cy++) {
            const int rb = cy * NCELL1D;
            const int s = g_off[rb + cx0];
            const int e = g_off[rb + cx1 + 1];
            for (int k = s; k < e; k++) {
                const float4 p = g_pts[k];
                const float dot = __fmaf_rn(p.y, gy, __fmul_rn(p.x, gx));
                const float d2 = __fsub_rn(__fadd_rn(p.z, g2),
                                           __fmul_rn(2.0f, dot));
                insert4(d2, g_pid[k], p.w,
                        d2a, d2b, d2c, d2d, ida, idb, idc, idd,
                        sca, scb, scc, scd);
            }
        }
    }

    // Finalize: d = sqrt(max(d2,1e-12)); filter (d <= 2*d0) & (d < dist_max);
    // pick max score, first occurrence wins ties (strict >).
    const float d0 = sqrtf(fmaxf(d2a, 1e-12f));
    const float thr = __fmul_rn(2.0f, d0);   // exact (power of 2)

    float best = NEG_INF_F;
    int bestid = 0;
    {
        const float dk = d0;
        if (dk <= thr && dk < dist_max && sca > best) { best = sca; bestid = ida; }
    }
    {
        const float dk = sqrtf(fmaxf(d2b, 1e-12f));
        if (dk <= thr && dk < dist_max && scb > best) { best = scb; bestid = idb; }
    }
    {
        const float dk = sqrtf(fmaxf(d2c, 1e-12f));
        if (dk <= thr && dk < dist_max && scc > best) { best = scc; bestid = idc; }
    }
    {
        const float dk = sqrtf(fmaxf(d2d, 1e-12f));
        if (dk <= thr && dk < dist_max && scd > best) { best = scd; bestid = idd; }
    }

    // Rows are 24 bytes -> float2-aligned.
    const float2* acc2 = (const float2*)accu;
    float2* out2 = (float2*)out;
    const float2 a01 = acc2[g * 3 + 0];
    const float2 a23 = acc2[g * 3 + 1];
    const float2 a45 = acc2[g * 3 + 2];

    if (best > a45.x) {
        const float4 pr = pos[bestid];
        const float code = *code_p;
        out2[g * 3 + 0] = make_float2(pr.x, pr.y);
        out2[g * 3 + 1] = make_float2(pr.z, pr.w);
        out2[g * 3 + 2] = make_float2(best, code);
    } else {
        out2[g * 3 + 0] = a01;
        out2[g * 3 + 1] = a23;
        out2[g * 3 + 2] = a45;
    }
}

// ---------------------------------------------------------------------------
extern "C" void kernel_launch(void* const* d_in, const int* in_sizes, int n_in,
                              void* d_out, int out_size)
{
    const float4* pos    = (const float4*)d_in[0];
    const float*  scores = (const float*) d_in[1];
    const float2* grid   = (const float2*)d_in[2];
    const float*  accu   = (const float*) d_in[3];
    const float*  scale  = (const float*) d_in[4];
    const float*  code   = (const float*) d_in[5];
    float* out = (float*)d_out;

    build_bins_kernel<<<1, 1024>>>(pos, scores);
    pump_main_kernel<<<G_TOTAL / 256, 256>>>(grid, pos, accu, scale, code, out);
}

// round 4
// speedup vs baseline: 1.6441x; 1.4837x over previous
#include <cuda_runtime.h>
#include <cfloat>
#include <climits>
#include <math.h>

#define NPTS     4096
#define G_TOTAL  65536
#define NBUCK    64
#define INV_CELL (1.0f / 16.0f)
#define NEG_INF_F (__int_as_float(0xff800000))

#define CAPB     12    // per-bucket capacity
#define OCAP     32    // overflow list capacity

// Monotonic float<->int key mapping (handles negatives)
__device__ __forceinline__ int f2ord(float f) {
    int i = __float_as_int(f);
    return (i >= 0) ? i : (i ^ 0x7fffffff);
}
__device__ __forceinline__ float ord2f(int i) {
    return __int_as_float((i >= 0) ? i : (i ^ 0x7fffffff));
}

// Lexicographic (d, pid) top-4 insertion — exactly matches top_k tie-breaking.
__device__ __forceinline__ void insert4(
    float d, int pid, float sc,
    float& da, float& db, float& dc, float& dd,
    int& ia, int& ib, int& ic, int& id_,
    float& sa, float& sb, float& sc_, float& sd)
{
    if (d < dd || (d == dd && pid < id_)) {
        dd = d; id_ = pid; sd = sc;
        if (dd < dc || (dd == dc && id_ < ic)) {
            float td = dc; int ti = ic; float ts = sc_;
            dc = dd; ic = id_; sc_ = sd;
            dd = td; id_ = ti; sd = ts;
            if (dc < db || (dc == db && ic < ib)) {
                td = db; ti = ib; ts = sb;
                db = dc; ib = ic; sb = sc_;
                dc = td; ic = ti; sc_ = ts;
                if (db < da || (db == da && ib < ia)) {
                    td = da; ti = ia; ts = sa;
                    da = db; ia = ib; sa = sb;
                    db = td; ib = ti; sb = ts;
                }
            }
        }
    }
}

// ---------------------------------------------------------------------------
// Single fused kernel. One block per 256 grid points (one grid row).
// Phase A: cooperative scan of all 4096 points -> smem x-buckets for the
//          block's y-strip. Phase B: per-thread windowed top-4 + select.
// ---------------------------------------------------------------------------
__global__ __launch_bounds__(256) void pump_fused_kernel(
    const float4* __restrict__ pos,      // (NPTS, 4)
    const float*  __restrict__ scores,   // (NPTS,)
    const float2* __restrict__ grid,     // (G, 2)
    const float*  __restrict__ accu,     // (G, 6)
    const float*  __restrict__ scale_p,
    const float*  __restrict__ code_p,
    float*        __restrict__ out)      // (G, 6)
{
    __shared__ float4 s_buck[NBUCK * CAPB];
    __shared__ int    s_bpid[NBUCK * CAPB];
    __shared__ int    s_cnt[NBUCK];
    __shared__ float4 s_ovf[OCAP];
    __shared__ int    s_opid[OCAP];
    __shared__ int    s_ocnt, s_fb, s_ymin, s_ymax;

    const int tid = threadIdx.x;
    const int g = blockIdx.x * 256 + tid;

    const float2 gp = grid[g];
    const float gx = gp.x, gy = gp.y;
    const float g2 = __fadd_rn(__fmul_rn(gx, gx), __fmul_rn(gy, gy));

    const float scale = *scale_p;
    const float dist_max = __fsub_rn(__fmul_rn(8.0f, scale), 1e-7f);
    const float r = dist_max;

    // ---- init smem + block y-range ----
    if (tid < NBUCK) s_cnt[tid] = 0;
    if (tid == 0) { s_ocnt = 0; s_fb = 0; s_ymin = INT_MAX; s_ymax = INT_MIN; }
    __syncthreads();
    atomicMin(&s_ymin, f2ord(gy));
    atomicMax(&s_ymax, f2ord(gy));
    __syncthreads();
    const float ylo = ord2f(s_ymin) - r;
    const float yhi = ord2f(s_ymax) + r;

    // ---- Phase A: scan all points, bin survivors into x-buckets ----
    #pragma unroll 4
    for (int i = 0; i < NPTS / 256; i++) {
        const int idx = tid + i * 256;
        const float4 p = pos[idx];
        if (p.y > ylo && p.y < yhi) {
            int bx = (int)floorf(p.x * INV_CELL);
            bx = min(NBUCK - 1, max(0, bx));
            const int slot = atomicAdd(&s_cnt[bx], 1);
            const float p2 = __fadd_rn(__fmul_rn(p.x, p.x), __fmul_rn(p.y, p.y));
            const float sc = scores[idx];
            const float4 e = make_float4(p.x, p.y, p2, sc);
            if (slot < CAPB) {
                s_buck[bx * CAPB + slot] = e;
                s_bpid[bx * CAPB + slot] = idx;
            } else {
                const int o = atomicAdd(&s_ocnt, 1);
                if (o < OCAP) { s_ovf[o] = e; s_opid[o] = idx; }
                else s_fb = 1;   // pathological input: full-scan fallback
            }
        }
    }
    __syncthreads();

    // ---- issue accu loads early (overlap with compute) ----
    const float2* acc2 = (const float2*)accu;
    const float2 a01 = acc2[g * 3 + 0];
    const float2 a23 = acc2[g * 3 + 1];
    const float2 a45 = acc2[g * 3 + 2];

    // ---- Phase B: top-4 by (d, pid) over the x-window ----
    float da = FLT_MAX, db = FLT_MAX, dc = FLT_MAX, dd = FLT_MAX;
    int   ia = INT_MAX, ib = INT_MAX, ic = INT_MAX, id_ = INT_MAX;
    float sa = 0.0f,    sb = 0.0f,    sc_ = 0.0f,   sd = 0.0f;

    if (!s_fb) {
        int bx0 = (int)floorf((gx - r) * INV_CELL);
        int bx1 = (int)floorf((gx + r) * INV_CELL);
        bx0 = min(NBUCK - 1, max(0, bx0));
        bx1 = min(NBUCK - 1, max(0, bx1));

        for (int bx = bx0; bx <= bx1; bx++) {
            const int n = min(s_cnt[bx], CAPB);
            const int base = bx * CAPB;
            for (int k = 0; k < n; k++) {
                const float4 e = s_buck[base + k];
                const int pid = s_bpid[base + k];
                const float dot = __fmaf_rn(e.y, gy, __fmul_rn(e.x, gx));
                const float d2 = __fsub_rn(__fadd_rn(e.z, g2),
                                           __fmul_rn(2.0f, dot));
                const float d = sqrtf(fmaxf(d2, 1e-12f));
                insert4(d, pid, e.w, da, db, dc, dd, ia, ib, ic, id_,
                        sa, sb, sc_, sd);
            }
        }
        const int on = min(s_ocnt, OCAP);
        for (int k = 0; k < on; k++) {
            const float4 e = s_ovf[k];
            const int pid = s_opid[k];
            const float dot = __fmaf_rn(e.y, gy, __fmul_rn(e.x, gx));
            const float d2 = __fsub_rn(__fadd_rn(e.z, g2),
                                       __fmul_rn(2.0f, dot));
            const float d = sqrtf(fmaxf(d2, 1e-12f));
            insert4(d, pid, e.w, da, db, dc, dd, ia, ib, ic, id_,
                    sa, sb, sc_, sd);
        }
    } else {
        // Fallback: scan everything from gmem (correct for any input).
        for (int idx = 0; idx < NPTS; idx++) {
            const float4 p = pos[idx];
            const float p2 = __fadd_rn(__fmul_rn(p.x, p.x), __fmul_rn(p.y, p.y));
            const float scv = scores[idx];
            const float dot = __fmaf_rn(p.y, gy, __fmul_rn(p.x, gx));
            const float d2 = __fsub_rn(__fadd_rn(p2, g2),
                                       __fmul_rn(2.0f, dot));
            const float d = sqrtf(fmaxf(d2, 1e-12f));
            insert4(d, idx, scv, da, db, dc, dd, ia, ib, ic, id_,
                    sa, sb, sc_, sd);
        }
    }

    // ---- Finalize: filter (d <= 2*d0) & (d < dist_max); max score,
    //      first occurrence wins ties (strict >) ----
    const float thr = __fmul_rn(2.0f, da);   // exact (power of 2)

    float best = NEG_INF_F;
    int bestid = 0;
    if (da <= thr && da < dist_max && sa  > best) { best = sa;  bestid = ia; }
    if (db <= thr && db < dist_max && sb  > best) { best = sb;  bestid = ib; }
    if (dc <= thr && dc < dist_max && sc_ > best) { best = sc_; bestid = ic; }
    if (dd <= thr && dd < dist_max && sd  > best) { best = sd;  bestid = id_; }

    float2* out2 = (float2*)out;
    if (best > a45.x) {
        const float4 pr = pos[bestid];
        const float code = *code_p;
        out2[g * 3 + 0] = make_float2(pr.x, pr.y);
        out2[g * 3 + 1] = make_float2(pr.z, pr.w);
        out2[g * 3 + 2] = make_float2(best, code);
    } else {
        out2[g * 3 + 0] = a01;
        out2[g * 3 + 1] = a23;
        out2[g * 3 + 2] = a45;
    }
}

// ---------------------------------------------------------------------------
// Inputs (metadata order): pos (4096,4) f32, scores (4096,) f32,
// grid (65536,2) f32, accu (65536,6) f32, scale () f32, code () f32.
// ---------------------------------------------------------------------------
extern "C" void kernel_launch(void* const* d_in, const int* in_sizes, int n_in,
                              void* d_out, int out_size)
{
    const float4* pos    = (const float4*)d_in[0];
    const float*  scores = (const float*) d_in[1];
    const float2* grid   = (const float2*)d_in[2];
    const float*  accu   = (const float*) d_in[3];
    const float*  scale  = (const float*) d_in[4];
    const float*  code   = (const float*) d_in[5];
    float* out = (float*)d_out;

    pump_fused_kernel<<<G_TOTAL / 256, 256>>>(pos, scores, grid, accu,
                                              scale, code, out);
}